// round 6
// baseline (speedup 1.0000x reference)
#include <cuda_runtime.h>
#include <cuda_fp16.h>
#include <math.h>

// Problem dims (fixed by the dataset)
#define NN 4
#define HH 512
#define WW 512
#define CC 64

#define CPB     32                 // channels per block (128B fp32 per row-step)
#define THREADS 512
#define ROWLEN  512                // scan length (W in pass1, H in pass2)
#define NCHUNK  (THREADS / CPB)    // 16
#define CLEN    (ROWLEN / NCHUNK)  // 32
#define LWARM   16                 // warm-up: err ~ 0.5^17 ~ 8e-6
#define VECH    (ROWLEN * CPB / 8) // uint4s (8 halves) per fp16 tile = 2048
#define VEC     (ROWLEN * CPB / 4) // float4-granule items (epilogue) = 4096
#define SMEM_BYTES (ROWLEN * CPB * 2) // 32768 (fp16 tile -> 4 CTAs/SM)

// Intermediate (W-filtered) image in fp16, same NHWC index space as x.
__device__ __half g_scratch[(size_t)NN * HH * WW * CC];

// Forward+backward first-order IIR (a=b=0.5) over a ROWLEN x CPB tile held
// in fp16 shared memory, in place. Carry chain fp32 in registers; only
// per-element storage rounds to fp16. Boundary chunks are EXACT w.r.t. the
// reference inits (carry = s[0] = x[0] fwd; carry = s[L-1] = y_f[L-1] bwd).
__device__ __forceinline__ void iir_scan_tile_h(__half* s, int tid) {
    const int c     = tid & (CPB - 1);
    const int chunk = tid / CPB;          // 0..NCHUNK-1
    const int w0    = chunk * CLEN;
    const int w1    = w0 + CLEN;

    int ws = w0 - LWARM; if (ws < 0) ws = 0;
    float carry = __half2float(s[ws * CPB + c]);
    for (int w = ws; w < w0; ++w)
        carry = fmaf(0.5f, carry, 0.5f * __half2float(s[w * CPB + c]));
    __syncthreads();

    #pragma unroll
    for (int w = w0; w < w1; ++w) {
        carry = fmaf(0.5f, carry, 0.5f * __half2float(s[w * CPB + c]));
        s[w * CPB + c] = __float2half_rn(carry);
    }
    __syncthreads();

    int we = w1 - 1 + LWARM; if (we > ROWLEN - 1) we = ROWLEN - 1;
    carry = __half2float(s[we * CPB + c]);
    for (int w = we - 1; w >= w1; --w)
        carry = fmaf(0.5f, carry, 0.5f * __half2float(s[w * CPB + c]));
    __syncthreads();

    #pragma unroll
    for (int w = w1 - 1; w >= w0; --w) {
        carry = fmaf(0.5f, carry, 0.5f * __half2float(s[w * CPB + c]));
        s[w * CPB + c] = __float2half_rn(carry);
    }
    __syncthreads();
}

// ---- role bodies (block-uniform) ----

// W-direction IIR for row `h` of image `n`: x (fp32) -> scan -> scratch fp16.
__device__ __forceinline__ void do_pass1(const float* __restrict__ x,
                                         int n, int h, int cg, __half* s16) {
    uint4* s4 = reinterpret_cast<uint4*>(s16);
    const size_t base = ((size_t)n * HH + h) * (WW * CC) + (size_t)cg * CPB;

    #pragma unroll
    for (int i = threadIdx.x; i < VECH; i += THREADS) {
        const int w = i >> 2;
        const int q = i & 3;
        const float4 a = *(const float4*)(x + base + (size_t)w * CC + q * 8);
        const float4 b = *(const float4*)(x + base + (size_t)w * CC + q * 8 + 4);
        __half2 hv[4];
        hv[0] = __floats2half2_rn(a.x, a.y);
        hv[1] = __floats2half2_rn(a.z, a.w);
        hv[2] = __floats2half2_rn(b.x, b.y);
        hv[3] = __floats2half2_rn(b.z, b.w);
        s4[w * 4 + q] = *(uint4*)hv;
    }
    __syncthreads();

    iir_scan_tile_h(s16, threadIdx.x);

    #pragma unroll
    for (int i = threadIdx.x; i < VECH; i += THREADS) {
        const int w = i >> 2;
        const int q = i & 3;
        *(uint4*)(g_scratch + base + (size_t)w * CC + q * 8) = s4[w * 4 + q];
    }
}

// H-direction IIR for column `w` of image `n` + residual mix -> out.
__device__ __forceinline__ void do_pass2(const float* __restrict__ x,
                                         const float* __restrict__ alpha,
                                         float* __restrict__ out,
                                         int n, int w, int cg, __half* s16) {
    uint4* s4 = reinterpret_cast<uint4*>(s16);
    __shared__ __align__(16) float sm[CPB];

    const size_t base = (size_t)n * (HH * WW * CC) + (size_t)w * CC + (size_t)cg * CPB;

    if (threadIdx.x < CPB) {
        const float a = alpha[cg * CPB + threadIdx.x];
        sm[threadIdx.x] = 1.0f / (1.0f + expf(-a));   // sigmoid mix
    }

    #pragma unroll
    for (int i = threadIdx.x; i < VECH; i += THREADS) {
        const int h = i >> 2;
        const int q = i & 3;
        s4[h * 4 + q] = *(const uint4*)(g_scratch + base + (size_t)h * (WW * CC) + q * 8);
    }
    __syncthreads();

    iir_scan_tile_h(s16, threadIdx.x);

    #pragma unroll
    for (int i = threadIdx.x; i < VEC; i += THREADS) {
        const int    h  = i >> 3;
        const int    c4 = i & 7;
        const size_t g  = base + (size_t)h * (WW * CC) + c4 * 4;
        const float4 xv = *(const float4*)(x + g);
        const __half2* hp = (const __half2*)(s16 + h * CPB + c4 * 4);
        const float2 y0 = __half22float2(hp[0]);
        const float2 y1 = __half22float2(hp[1]);
        const float4 mv = *(const float4*)(&sm[c4 * 4]);
        float4 o;
        o.x = fmaf(mv.x, y0.x - xv.x, xv.x);
        o.y = fmaf(mv.y, y0.y - xv.y, xv.y);
        o.z = fmaf(mv.z, y1.x - xv.z, xv.z);
        o.w = fmaf(mv.w, y1.y - xv.w, xv.w);
        *(float4*)(out + g) = o;
    }
}

// ---- kernels ----

__global__ void __launch_bounds__(THREADS, 4)
pass1_kernel(const float* __restrict__ x, int n) {
    extern __shared__ __half s16[];
    do_pass1(x, n, blockIdx.x, blockIdx.y, s16);
}

__global__ void __launch_bounds__(THREADS, 4)
pass2_kernel(const float* __restrict__ x, const float* __restrict__ alpha,
             float* __restrict__ out, int n) {
    extern __shared__ __half s16[];
    do_pass2(x, alpha, out, n, blockIdx.x, blockIdx.y, s16);
}

// Mixed-role launch: even blocks run pass1(image n1), odd blocks run
// pass2(image n2 = n1-1). No data dependency between the two roles within
// a launch; the parity interleave co-schedules both roles on every SM so
// pass1's serial-scan bubbles are covered by pass2's memory traffic.
__global__ void __launch_bounds__(THREADS, 4)
fused_kernel(const float* __restrict__ x, const float* __restrict__ alpha,
             float* __restrict__ out, int n1, int n2) {
    extern __shared__ __half s16[];
    const int idx = blockIdx.x >> 1;
    if ((blockIdx.x & 1) == 0)
        do_pass1(x, n1, idx, blockIdx.y, s16);
    else
        do_pass2(x, alpha, out, n2, idx, blockIdx.y, s16);
}

extern "C" void kernel_launch(void* const* d_in, const int* in_sizes, int n_in,
                              void* d_out, int out_size) {
    const float* x     = (const float*)d_in[0];
    const float* alpha = (const float*)d_in[1];
    float*       out   = (float*)d_out;

    dim3 gsingle(ROWLEN, CC / CPB);        // (512, 2)
    dim3 gfused(2 * ROWLEN, CC / CPB);     // (1024, 2)

    pass1_kernel<<<gsingle, THREADS, SMEM_BYTES>>>(x, 0);
    fused_kernel<<<gfused, THREADS, SMEM_BYTES>>>(x, alpha, out, 1, 0);
    fused_kernel<<<gfused, THREADS, SMEM_BYTES>>>(x, alpha, out, 2, 1);
    fused_kernel<<<gfused, THREADS, SMEM_BYTES>>>(x, alpha, out, 3, 2);
    pass2_kernel<<<gsingle, THREADS, SMEM_BYTES>>>(x, alpha, out, 3);
}

// round 7
// speedup vs baseline: 1.2881x; 1.2881x over previous
#include <cuda_runtime.h>
#include <cuda_fp16.h>
#include <math.h>

// Problem dims (fixed by the dataset)
#define NN 4
#define HH 512
#define WW 512
#define CC 64

#define CPB     64                 // channels per block = full row (256B fp32)
#define THREADS 512
#define ROWLEN  512
#define NCHUNK  16                 // one warp per chunk, lane = half2 channel pair
#define CLEN    (ROWLEN / NCHUNK)  // 32
#define LWARM   16                 // warm-up: err ~ 0.5^17 ~ 8e-6
#define H2PW    (CPB / 2)          // half2 per w = 32
#define VECH    (ROWLEN * CPB / 8) // uint4 (8 halves) per fp16 tile = 4096
#define VEC     (ROWLEN * CPB / 4) // float4 items (epilogue) = 8192
#define SMEM_BYTES (ROWLEN * CPB * 2) // 65536 (fp16 tile -> 3 CTAs/SM)

// Intermediate (W-filtered) image in fp16, same NHWC index space as x.
__device__ __half g_scratch[(size_t)NN * HH * WW * CC];

// Forward+backward first-order IIR (a=b=0.5) over a ROWLEN x CC tile held as
// half2 in shared memory, in place. Each thread runs TWO independent fp32
// carry chains (one half2 = 2 channels); chains pipeline in the FMA unit so
// the serial wall time is unchanged. Boundary chunks are EXACT w.r.t. the
// reference inits (carry = s[0] = x[0] fwd; carry = s[L-1] = y_f[L-1] bwd).
// Warp lanes address 32 consecutive half2 (128B) -> conflict-free.
__device__ __forceinline__ void iir_scan_tile_h2(__half2* s, int tid) {
    const int c     = tid & 31;           // half2 index within row
    const int chunk = tid >> 5;           // 0..15
    const int w0    = chunk * CLEN;
    const int w1    = w0 + CLEN;

    // ---- forward warm-up (read-only) ----
    int ws = w0 - LWARM; if (ws < 0) ws = 0;
    float2 carry = __half22float2(s[ws * H2PW + c]);
    for (int w = ws; w < w0; ++w) {
        const float2 v = __half22float2(s[w * H2PW + c]);
        carry.x = fmaf(0.5f, carry.x, 0.5f * v.x);
        carry.y = fmaf(0.5f, carry.y, 0.5f * v.y);
    }
    __syncthreads();

    // ---- forward scan, in place ----
    #pragma unroll
    for (int w = w0; w < w1; ++w) {
        const float2 v = __half22float2(s[w * H2PW + c]);
        carry.x = fmaf(0.5f, carry.x, 0.5f * v.x);
        carry.y = fmaf(0.5f, carry.y, 0.5f * v.y);
        s[w * H2PW + c] = __floats2half2_rn(carry.x, carry.y);
    }
    __syncthreads();

    // ---- backward warm-up (read-only on finalized y_f) ----
    int we = w1 - 1 + LWARM; if (we > ROWLEN - 1) we = ROWLEN - 1;
    carry = __half22float2(s[we * H2PW + c]);
    for (int w = we - 1; w >= w1; --w) {
        const float2 v = __half22float2(s[w * H2PW + c]);
        carry.x = fmaf(0.5f, carry.x, 0.5f * v.x);
        carry.y = fmaf(0.5f, carry.y, 0.5f * v.y);
    }
    __syncthreads();

    // ---- backward scan, in place ----
    #pragma unroll
    for (int w = w1 - 1; w >= w0; --w) {
        const float2 v = __half22float2(s[w * H2PW + c]);
        carry.x = fmaf(0.5f, carry.x, 0.5f * v.x);
        carry.y = fmaf(0.5f, carry.y, 0.5f * v.y);
        s[w * H2PW + c] = __floats2half2_rn(carry.x, carry.y);
    }
    __syncthreads();
}

// Pass 1: IIR along W. One block per (n*H) row, ALL 64 channels.
__global__ void __launch_bounds__(THREADS, 3)
pass1_kernel(const float* __restrict__ x) {
    extern __shared__ __half2 s2[];
    uint4* s4 = reinterpret_cast<uint4*>(s2);

    const int    nh   = blockIdx.x;                 // n*HH + h
    const size_t base = (size_t)nh * (WW * CC);

    // Load + fp32->fp16: per w, 64 ch = 8 uint4 of 8 halves (two float4 each).
    #pragma unroll
    for (int i = threadIdx.x; i < VECH; i += THREADS) {
        const int w = i >> 3;
        const int q = i & 7;
        const float4 a = *(const float4*)(x + base + (size_t)w * CC + q * 8);
        const float4 b = *(const float4*)(x + base + (size_t)w * CC + q * 8 + 4);
        __half2 hv[4];
        hv[0] = __floats2half2_rn(a.x, a.y);
        hv[1] = __floats2half2_rn(a.z, a.w);
        hv[2] = __floats2half2_rn(b.x, b.y);
        hv[3] = __floats2half2_rn(b.z, b.w);
        s4[w * 8 + q] = *(uint4*)hv;
    }
    __syncthreads();

    iir_scan_tile_h2(s2, threadIdx.x);

    // Raw fp16 copy smem -> scratch: per w, 64 ch = 128B = 8 uint4.
    #pragma unroll
    for (int i = threadIdx.x; i < VECH; i += THREADS) {
        const int w = i >> 3;
        const int q = i & 7;
        *(uint4*)(g_scratch + base + (size_t)w * CC + q * 8) = s4[w * 8 + q];
    }
}

// Pass 2: IIR along H on the scratch (raw fp16 in), residual mix -> out.
__global__ void __launch_bounds__(THREADS, 3)
pass2_kernel(const float* __restrict__ x,
             const float* __restrict__ alpha,
             float*       __restrict__ out) {
    extern __shared__ __half2 s2[];
    uint4* s4 = reinterpret_cast<uint4*>(s2);
    __shared__ __align__(16) float sm[CPB];

    const int    nw   = blockIdx.x;                 // n*WW + w
    const int    n    = nw >> 9;
    const int    w    = nw & 511;
    const size_t base = (size_t)n * (HH * WW * CC) + (size_t)w * CC;

    if (threadIdx.x < CPB)
        sm[threadIdx.x] = 1.0f / (1.0f + expf(-alpha[threadIdx.x]));

    // Raw fp16 copy scratch -> smem: per h, 8 uint4 (128B row-step).
    #pragma unroll
    for (int i = threadIdx.x; i < VECH; i += THREADS) {
        const int h = i >> 3;
        const int q = i & 7;
        s4[h * 8 + q] = *(const uint4*)(g_scratch + base + (size_t)h * (WW * CC) + q * 8);
    }
    __syncthreads();

    iir_scan_tile_h2(s2, threadIdx.x);

    // Epilogue: y (fp16 smem) + x (fp32 gmem) -> out (fp32). 256B/row-step.
    #pragma unroll
    for (int i = threadIdx.x; i < VEC; i += THREADS) {
        const int    h  = i >> 4;                   // 16 float4 per h
        const int    c4 = i & 15;
        const size_t g  = base + (size_t)h * (WW * CC) + c4 * 4;
        const float4 xv = *(const float4*)(x + g);
        const __half2* hp = (const __half2*)(s2 + h * H2PW + c4 * 2);
        const float2 y0 = __half22float2(hp[0]);
        const float2 y1 = __half22float2(hp[1]);
        const float4 mv = *(const float4*)(&sm[c4 * 4]);
        float4 o;
        o.x = fmaf(mv.x, y0.x - xv.x, xv.x);
        o.y = fmaf(mv.y, y0.y - xv.y, xv.y);
        o.z = fmaf(mv.z, y1.x - xv.z, xv.z);
        o.w = fmaf(mv.w, y1.y - xv.w, xv.w);
        *(float4*)(out + g) = o;
    }
}

extern "C" void kernel_launch(void* const* d_in, const int* in_sizes, int n_in,
                              void* d_out, int out_size) {
    const float* x     = (const float*)d_in[0];
    const float* alpha = (const float*)d_in[1];
    float*       out   = (float*)d_out;

    // >48KB dynamic smem opt-in (idempotent, capture-safe).
    cudaFuncSetAttribute(pass1_kernel,
                         cudaFuncAttributeMaxDynamicSharedMemorySize, SMEM_BYTES);
    cudaFuncSetAttribute(pass2_kernel,
                         cudaFuncAttributeMaxDynamicSharedMemorySize, SMEM_BYTES);

    pass1_kernel<<<NN * HH, THREADS, SMEM_BYTES>>>(x);
    pass2_kernel<<<NN * WW, THREADS, SMEM_BYTES>>>(x, alpha, out);
}